// round 11
// baseline (speedup 1.0000x reference)
#include <cuda_runtime.h>

// ---------------- scratch (device globals; zero-initialized) ---------------
__device__ float g_pooledp[16*256*32];     // [b][cs][32] padded, pads stay 0
__device__ float g_dots[1281];             // Wq^T bk | Wk^T bq | bq.bk
__device__ float g_wqk[1024*256];          // Wq^T Wk  [cr][cs]
__device__ float g_kq[16*1024*32];         // [b][cr][32]
__device__ float g_v[16*1024*32];          // [b][cr][32]
__device__ float g_bqk[16*32];             // [b][32]
__device__ float g_epart[4*16*784*32];     // [z][b][n][32]
__device__ float g_attn_t[16*25*784];      // [b][s][n]  TRANSPOSED attention
__device__ int   g_cnt[16*7];              // completion counters [b][ntile]

// ---------------- packed f32x2 helpers -------------------------------------
__device__ __forceinline__ unsigned long long pack2(float lo, float hi) {
    unsigned long long r;
    asm("mov.b64 %0, {%1,%2};" : "=l"(r) : "f"(lo), "f"(hi));
    return r;
}
__device__ __forceinline__ float2 unpack2(unsigned long long v) {
    float2 r;
    asm("mov.b64 {%0,%1}, %2;" : "=f"(r.x), "=f"(r.y) : "l"(v));
    return r;
}
__device__ __forceinline__ void fma2(unsigned long long& d,
                                     unsigned long long a,
                                     unsigned long long b) {
    asm("fma.rn.f32x2 %0, %1, %2, %0;" : "+l"(d) : "l"(a), "l"(b));
}

// ---------------------------------------------------------------------------
// k_prep: gemm0 (0..255) | dots1 (256..287) | dots2 (288..295) | dots3 (296)
//         | pool (297..1896)
// ---------------------------------------------------------------------------
__global__ __launch_bounds__(128) void k_prep(const float* __restrict__ Wq,
                                              const float* __restrict__ bq,
                                              const float* __restrict__ Wk,
                                              const float* __restrict__ bk,
                                              const float* __restrict__ xs_in) {
    __shared__ float sm[1664];
    int bid = blockIdx.x;
    int t = threadIdx.x;

    if (bid < 256) {
        float* As = sm;          // [16][32]
        float* Bs = sm + 512;    // [16][32]
        int m0 = (bid >> 3) * 32, n0 = (bid & 7) * 32;
        int tx = t & 7, ty = t >> 3;
        unsigned long long acc2[2][2] = {};
        for (int k0 = 0; k0 < 512; k0 += 16) {
            #pragma unroll
            for (int u = 0; u < 4; u++) {
                int idx = t + u * 128;
                int kk = idx >> 5, mm = idx & 31;
                As[idx] = Wq[(k0+kk)*1024 + m0 + mm];
                Bs[idx] = Wk[(k0+kk)*256 + n0 + mm];
            }
            __syncthreads();
            #pragma unroll
            for (int kk = 0; kk < 16; kk++) {
                float2 a2 = *(const float2*)&As[kk*32 + ty*2];
                ulonglong2 b2 = *(const ulonglong2*)&Bs[kk*32 + tx*4];
                unsigned long long pa0 = pack2(a2.x, a2.x);
                unsigned long long pa1 = pack2(a2.y, a2.y);
                fma2(acc2[0][0], pa0, b2.x);
                fma2(acc2[0][1], pa0, b2.y);
                fma2(acc2[1][0], pa1, b2.x);
                fma2(acc2[1][1], pa1, b2.y);
            }
            __syncthreads();
        }
        #pragma unroll
        for (int i = 0; i < 2; i++) {
            float2 p0 = unpack2(acc2[i][0]), p1 = unpack2(acc2[i][1]);
            *(float4*)&g_wqk[(m0 + ty*2 + i)*256 + n0 + tx*4] =
                make_float4(p0.x, p0.y, p1.x, p1.y);
        }
    } else if (bid < 288) {
        int lane = t & 31, slice = t >> 5;
        int c = (bid - 256) * 32 + lane;
        float acc = 0.f;
        int kbase = slice * 128;
        #pragma unroll 8
        for (int i = 0; i < 128; i++)
            acc += Wq[(kbase + i)*1024 + c] * bk[kbase + i];
        sm[t] = acc; __syncthreads();
        if (t < 32)
            g_dots[(bid - 256)*32 + t] = sm[t] + sm[t+32] + sm[t+64] + sm[t+96];
    } else if (bid < 296) {
        int lane = t & 31, slice = t >> 5;
        int c = (bid - 288) * 32 + lane;
        float acc = 0.f;
        int kbase = slice * 128;
        #pragma unroll 8
        for (int i = 0; i < 128; i++)
            acc += Wk[(kbase + i)*256 + c] * bq[kbase + i];
        sm[t] = acc; __syncthreads();
        if (t < 32)
            g_dots[1024 + (bid - 288)*32 + t] = sm[t] + sm[t+32] + sm[t+64] + sm[t+96];
    } else if (bid == 296) {
        float acc = 0.f;
        for (int i = t; i < 512; i += 128) acc += bq[i] * bk[i];
        sm[t] = acc; __syncthreads();
        for (int st = 64; st > 0; st >>= 1) {
            if (t < st) sm[t] += sm[t + st];
            __syncthreads();
        }
        if (t == 0) g_dots[1280] = sm[0];
    } else {
        int r0 = (bid - 297) * 64;
        const float* src = xs_in + (size_t)r0 * 25;
        for (int i = t; i < 1600; i += 128) sm[i] = src[i];
        __syncthreads();
        if (t < 64) {
            float s = 0.f;
            #pragma unroll
            for (int w = 0; w < 25; w++) s += sm[t*25 + w];
            int o = r0 + t;
            int bc = o / 25, s_idx = o - bc * 25;
            g_pooledp[bc*32 + s_idx] = s * (1.0f / 25.0f);
        }
    }
}

// ---------------------------------------------------------------------------
// k_gemm1: [kq; v; bqk](b) = [Wqk; Wv; wkbq] @ pooledp_b + bias
// grid(17, 16), 256 thr (8 warps). BM=128, S=32, BK=32. thread 4m x 4s.
// ---------------------------------------------------------------------------
__global__ __launch_bounds__(256) void k_gemm1(const float* __restrict__ Wv,
                                               const float* __restrict__ bv) {
    __shared__ float As[32*132];
    __shared__ float Bs[32*32];
    int bx = blockIdx.x;
    int b  = blockIdx.y;
    int m0 = bx * 128;
    int t = threadIdx.x;
    int row = t >> 1, half = t & 1;
    int tx = t & 7, ty = t >> 3;
    unsigned long long acc2[4][2] = {};

    const float* arow;
    bool arow_valid;
    if (bx < 8)       { arow = g_wqk + (size_t)(m0 + row) * 256; arow_valid = true; }
    else if (bx < 16) { arow = Wv + (size_t)(m0 - 1024 + row) * 256; arow_valid = true; }
    else              { arow = g_dots + 1024; arow_valid = (row == 0); }

    for (int k0 = 0; k0 < 256; k0 += 32) {
        if (arow_valid) {
            #pragma unroll
            for (int u = 0; u < 4; u++) {
                int koff = half*16 + u*4;
                float4 a4 = *(const float4*)&arow[k0 + koff];
                As[(koff+0)*132 + row] = a4.x;
                As[(koff+1)*132 + row] = a4.y;
                As[(koff+2)*132 + row] = a4.z;
                As[(koff+3)*132 + row] = a4.w;
            }
        } else {
            #pragma unroll
            for (int u = 0; u < 4; u++) {
                int koff = half*16 + u*4;
                As[(koff+0)*132 + row] = 0.f;
                As[(koff+1)*132 + row] = 0.f;
                As[(koff+2)*132 + row] = 0.f;
                As[(koff+3)*132 + row] = 0.f;
            }
        }
        const float4* bsrc = (const float4*)(g_pooledp + ((b << 8) + k0) * 32);
        ((float4*)Bs)[t] = bsrc[t];
        __syncthreads();
        #pragma unroll 8
        for (int kk = 0; kk < 32; kk++) {
            float4 a4 = *(const float4*)&As[kk*132 + ty*4];
            ulonglong2 b2 = *(const ulonglong2*)&Bs[kk*32 + tx*4];
            unsigned long long pa[4] = {pack2(a4.x,a4.x), pack2(a4.y,a4.y),
                                        pack2(a4.z,a4.z), pack2(a4.w,a4.w)};
            #pragma unroll
            for (int i = 0; i < 4; i++) {
                fma2(acc2[i][0], pa[i], b2.x);
                fma2(acc2[i][1], pa[i], b2.y);
            }
        }
        __syncthreads();
    }
    int s0 = tx * 4;
    #pragma unroll
    for (int i = 0; i < 4; i++) {
        int m = m0 + ty*4 + i;
        float2 p0 = unpack2(acc2[i][0]), p1 = unpack2(acc2[i][1]);
        if (bx < 8) {
            float d = g_dots[m];
            *(float4*)&g_kq[((b << 10) + m)*32 + s0] =
                make_float4(p0.x+d, p0.y+d, p1.x+d, p1.y+d);
        } else if (bx < 16) {
            float d = bv[m - 1024];
            *(float4*)&g_v[((b << 10) + (m - 1024))*32 + s0] =
                make_float4(p0.x+d, p0.y+d, p1.x+d, p1.y+d);
        } else if (m == 2048) {
            float d = g_dots[1280];
            *(float4*)&g_bqk[b*32 + s0] =
                make_float4(p0.x+d, p0.y+d, p1.x+d, p1.y+d);
        }
    }
}

// ---------------------------------------------------------------------------
// k_energy: epart[z,b,n,s] = sum_{c in z-chunk} x[c,n]*kq[c,s], then the
// LAST z-block for each (n-tile,b) sums partials, softmaxes, writes attn_t.
// grid(7, 16, 4), 224 thr. thread 4n x 4s.
// ---------------------------------------------------------------------------
__global__ __launch_bounds__(224) void k_energy(const float* __restrict__ x) {
    __shared__ float xs[64*112];
    __shared__ float kqs[64*32];
    __shared__ int s_last;
    int n0 = blockIdx.x * 112;
    int b  = blockIdx.y;
    int z  = blockIdx.z;
    int t = threadIdx.x;
    int nq = t % 28, sg = t / 28;
    unsigned long long acc2[4][2] = {};

    for (int cz = 0; cz < 4; cz++) {
        int cbase = z * 256 + cz * 64;
        const float4* xsrc = (const float4*)x
            + (size_t)((b << 10) + cbase) * 196 + (n0 >> 2);
        #pragma unroll
        for (int u = 0; u < 8; u++) {
            int cc = sg + u * 8;
            *(float4*)&xs[cc*112 + nq*4] = xsrc[(size_t)cc*196 + nq];
        }
        const float4* kq4 = (const float4*)(g_kq + (size_t)((b << 10) + cbase)*32);
        float4* kqs4 = (float4*)kqs;
        kqs4[t] = kq4[t];
        if (t + 224 < 512) kqs4[t + 224] = kq4[t + 224];
        if (t < 512 - 448) kqs4[t + 448] = kq4[t + 448];
        __syncthreads();
        #pragma unroll 8
        for (int cc = 0; cc < 64; cc++) {
            float4 x4 = *(const float4*)&xs[cc*112 + nq*4];
            ulonglong2 k2 = *(const ulonglong2*)&kqs[cc*32 + sg*4];
            unsigned long long px[4] = {pack2(x4.x,x4.x), pack2(x4.y,x4.y),
                                        pack2(x4.z,x4.z), pack2(x4.w,x4.w)};
            #pragma unroll
            for (int i = 0; i < 4; i++) {
                fma2(acc2[i][0], px[i], k2.x);
                fma2(acc2[i][1], px[i], k2.y);
            }
        }
        __syncthreads();
    }
    float* ep = g_epart + (size_t)(z*16 + b)*784*32;
    #pragma unroll
    for (int i = 0; i < 4; i++) {
        int n = n0 + nq*4 + i;
        float2 p0 = unpack2(acc2[i][0]), p1 = unpack2(acc2[i][1]);
        *(float4*)&ep[(size_t)n*32 + sg*4] = make_float4(p0.x, p0.y, p1.x, p1.y);
    }

    // ---- last-block-arrives softmax ----
    __threadfence();
    __syncthreads();
    if (t == 0)
        s_last = (atomicAdd(&g_cnt[b*7 + blockIdx.x], 1) == 3) ? 1 : 0;
    __syncthreads();
    if (s_last == 0) return;

    if (t < 112) {
        int n = n0 + t;
        const size_t part = (size_t)16*784*32;
        const float* base = g_epart + ((size_t)b*784 + n)*32;
        float4 v0 = *(const float4*)base;
        float4 v1 = *(const float4*)(base + 4);
        float4 v2 = *(const float4*)(base + 8);
        float4 v3 = *(const float4*)(base + 12);
        float4 v4 = *(const float4*)(base + 16);
        float4 v5 = *(const float4*)(base + 20);
        float4 v6 = *(const float4*)(base + 24);
        #pragma unroll
        for (int zz = 1; zz < 4; zz++) {
            const float* bz = base + zz*part;
            float4 u0 = *(const float4*)bz;
            float4 u1 = *(const float4*)(bz + 4);
            float4 u2 = *(const float4*)(bz + 8);
            float4 u3 = *(const float4*)(bz + 12);
            float4 u4 = *(const float4*)(bz + 16);
            float4 u5 = *(const float4*)(bz + 20);
            float4 u6 = *(const float4*)(bz + 24);
            v0.x+=u0.x; v0.y+=u0.y; v0.z+=u0.z; v0.w+=u0.w;
            v1.x+=u1.x; v1.y+=u1.y; v1.z+=u1.z; v1.w+=u1.w;
            v2.x+=u2.x; v2.y+=u2.y; v2.z+=u2.z; v2.w+=u2.w;
            v3.x+=u3.x; v3.y+=u3.y; v3.z+=u3.z; v3.w+=u3.w;
            v4.x+=u4.x; v4.y+=u4.y; v4.z+=u4.z; v4.w+=u4.w;
            v5.x+=u5.x; v5.y+=u5.y; v5.z+=u5.z; v5.w+=u5.w;
            v6.x+=u6.x; v6.y+=u6.y; v6.z+=u6.z; v6.w+=u6.w;
        }
        float e[25] = {v0.x,v0.y,v0.z,v0.w, v1.x,v1.y,v1.z,v1.w,
                       v2.x,v2.y,v2.z,v2.w, v3.x,v3.y,v3.z,v3.w,
                       v4.x,v4.y,v4.z,v4.w, v5.x,v5.y,v5.z,v5.w, v6.x};
        float mx = -1e30f;
        #pragma unroll
        for (int s = 0; s < 25; s++) {
            e[s] += g_bqk[b*32 + s];
            mx = fmaxf(mx, e[s]);
        }
        float sum = 0.f;
        #pragma unroll
        for (int s = 0; s < 25; s++) { e[s] = __expf(e[s] - mx); sum += e[s]; }
        float inv = 1.f / sum;
        float* at = g_attn_t + (size_t)b*25*784 + n;
        #pragma unroll
        for (int s = 0; s < 25; s++) at[(size_t)s*784] = e[s] * inv;
    }
    // reset counter for the next graph replay (safe: stream-ordered)
    if (t == 0) g_cnt[b*7 + blockIdx.x] = 0;
}

// ---------------------------------------------------------------------------
// k_out: out[c,n] = x[c,n] + gamma * sum_s v[c,s]*attn_t[s,n]
// grid(7, 16, 16), 224 thr. thread 4c x 8n.
// ---------------------------------------------------------------------------
__global__ __launch_bounds__(224) void k_out(const float* __restrict__ x,
                                             const float* __restrict__ gamma_p,
                                             float* __restrict__ out) {
    __shared__ float attn_ts[25*116];
    __shared__ float v_ts[25*68];
    int n0 = blockIdx.x * 112;
    int c0 = blockIdx.y * 64;
    int b  = blockIdx.z;
    int t = threadIdx.x;

    const float4* at4 = (const float4*)(g_attn_t + (size_t)b*25*784 + n0);
    #pragma unroll
    for (int u = 0; u < 4; u++) {
        int i = t + u*224;
        if (i < 700) {
            int s = i / 28, q = i - s*28;
            ((float4*)attn_ts)[s*29 + q] = at4[(size_t)s*196 + q];
        }
    }
    const float4* v4p = (const float4*)(g_v + (size_t)((b << 10) + c0)*32);
    #pragma unroll
    for (int u = 0; u < 3; u++) {
        int i = t + u*224;
        if (i < 512) {
            int row = i >> 3, q = i & 7;
            float4 a4 = v4p[row*8 + q];
            int s = q*4;
            if (s   < 25) v_ts[(s  )*68 + row] = a4.x;
            if (s+1 < 25) v_ts[(s+1)*68 + row] = a4.y;
            if (s+2 < 25) v_ts[(s+2)*68 + row] = a4.z;
            if (s+3 < 25) v_ts[(s+3)*68 + row] = a4.w;
        }
    }
    __syncthreads();

    int ng = t % 14, cq = t / 14;
    unsigned long long acc2[4][4] = {};
    #pragma unroll
    for (int s = 0; s < 25; s++) {
        float4 v4 = *(const float4*)&v_ts[s*68 + cq*4];
        const ulonglong2* ap = (const ulonglong2*)&attn_ts[s*116 + ng*8];
        ulonglong2 A0 = ap[0], A1 = ap[1];
        unsigned long long pv[4] = {pack2(v4.x,v4.x), pack2(v4.y,v4.y),
                                    pack2(v4.z,v4.z), pack2(v4.w,v4.w)};
        #pragma unroll
        for (int i = 0; i < 4; i++) {
            fma2(acc2[i][0], pv[i], A0.x);
            fma2(acc2[i][1], pv[i], A0.y);
            fma2(acc2[i][2], pv[i], A1.x);
            fma2(acc2[i][3], pv[i], A1.y);
        }
    }
    float gamma = gamma_p[0];
    #pragma unroll
    for (int i = 0; i < 4; i++) {
        int c = c0 + cq*4 + i;
        size_t off = (size_t)((b << 10) + c)*784 + n0 + ng*8;
        const float* xr = x + off;
        float* orow = out + off;
        float2 q0 = unpack2(acc2[i][0]), q1 = unpack2(acc2[i][1]);
        float2 q2 = unpack2(acc2[i][2]), q3 = unpack2(acc2[i][3]);
        float4 xa = *(const float4*)xr;
        float4 xc = *(const float4*)(xr + 4);
        *(float4*)orow = make_float4(fmaf(gamma,q0.x,xa.x), fmaf(gamma,q0.y,xa.y),
                                     fmaf(gamma,q1.x,xa.z), fmaf(gamma,q1.y,xa.w));
        *(float4*)(orow+4) = make_float4(fmaf(gamma,q2.x,xc.x), fmaf(gamma,q2.y,xc.y),
                                         fmaf(gamma,q3.x,xc.z), fmaf(gamma,q3.y,xc.w));
    }
}

// ---------------------------------------------------------------------------
extern "C" void kernel_launch(void* const* d_in, const int* in_sizes, int n_in,
                              void* d_out, int out_size) {
    const float* x_rgb  = (const float*)d_in[0];
    const float* x_skel = (const float*)d_in[1];
    const float* Wq     = (const float*)d_in[2];
    const float* bq     = (const float*)d_in[3];
    const float* Wk     = (const float*)d_in[4];
    const float* bk     = (const float*)d_in[5];
    const float* Wv     = (const float*)d_in[6];
    const float* bv     = (const float*)d_in[7];
    const float* gamma  = (const float*)d_in[8];
    float* out = (float*)d_out;

    k_prep  <<<1897, 128>>>(Wq, bq, Wk, bk, x_skel);
    k_gemm1 <<<dim3(17, 16), 256>>>(Wv, bv);
    k_energy<<<dim3(7, 16, 4), 224>>>(x_rgb);
    k_out   <<<dim3(7, 16, 16), 224>>>(x_rgb, gamma, out);
}

// round 12
// speedup vs baseline: 1.0803x; 1.0803x over previous
#include <cuda_runtime.h>

// ---------------- scratch (device globals; zero-initialized) ---------------
__device__ float g_pooledp[16*256*32];     // [b][cs][32] padded, pads stay 0
__device__ float g_dots[1281];             // Wq^T bk | Wk^T bq | bq.bk
__device__ float g_wqk[1024*256];          // Wq^T Wk  [cr][cs]
__device__ float g_kq[16*1024*32];         // [b][cr][32]
__device__ float g_v[16*1024*32];          // [b][cr][32]
__device__ float g_bqk[16*32];             // [b][32]
__device__ float g_epart[4*16*784*32];     // [z][b][n][32]
__device__ float g_attn_t[16*25*784];      // [b][s][n]  TRANSPOSED attention
__device__ int   g_cnt[16*7];              // completion counters [b][ntile]

// ---------------- packed f32x2 helpers -------------------------------------
__device__ __forceinline__ unsigned long long pack2(float lo, float hi) {
    unsigned long long r;
    asm("mov.b64 %0, {%1,%2};" : "=l"(r) : "f"(lo), "f"(hi));
    return r;
}
__device__ __forceinline__ float2 unpack2(unsigned long long v) {
    float2 r;
    asm("mov.b64 {%0,%1}, %2;" : "=f"(r.x), "=f"(r.y) : "l"(v));
    return r;
}
__device__ __forceinline__ void fma2(unsigned long long& d,
                                     unsigned long long a,
                                     unsigned long long b) {
    asm("fma.rn.f32x2 %0, %1, %2, %0;" : "+l"(d) : "l"(a), "l"(b));
}

// ---------------------------------------------------------------------------
// k_prep: gemm0 (0..255) | dots1 (256..287) | dots2 (288..295) | dots3 (296)
//         | pool (297..1896)
// ---------------------------------------------------------------------------
__global__ __launch_bounds__(128) void k_prep(const float* __restrict__ Wq,
                                              const float* __restrict__ bq,
                                              const float* __restrict__ Wk,
                                              const float* __restrict__ bk,
                                              const float* __restrict__ xs_in) {
    __shared__ float sm[1664];
    int bid = blockIdx.x;
    int t = threadIdx.x;

    if (bid < 256) {
        float* As = sm;          // [16][32]
        float* Bs = sm + 512;    // [16][32]
        int m0 = (bid >> 3) * 32, n0 = (bid & 7) * 32;
        int tx = t & 7, ty = t >> 3;
        unsigned long long acc2[2][2] = {};
        for (int k0 = 0; k0 < 512; k0 += 16) {
            #pragma unroll
            for (int u = 0; u < 4; u++) {
                int idx = t + u * 128;
                int kk = idx >> 5, mm = idx & 31;
                As[idx] = Wq[(k0+kk)*1024 + m0 + mm];
                Bs[idx] = Wk[(k0+kk)*256 + n0 + mm];
            }
            __syncthreads();
            #pragma unroll
            for (int kk = 0; kk < 16; kk++) {
                float2 a2 = *(const float2*)&As[kk*32 + ty*2];
                ulonglong2 b2 = *(const ulonglong2*)&Bs[kk*32 + tx*4];
                unsigned long long pa0 = pack2(a2.x, a2.x);
                unsigned long long pa1 = pack2(a2.y, a2.y);
                fma2(acc2[0][0], pa0, b2.x);
                fma2(acc2[0][1], pa0, b2.y);
                fma2(acc2[1][0], pa1, b2.x);
                fma2(acc2[1][1], pa1, b2.y);
            }
            __syncthreads();
        }
        #pragma unroll
        for (int i = 0; i < 2; i++) {
            float2 p0 = unpack2(acc2[i][0]), p1 = unpack2(acc2[i][1]);
            *(float4*)&g_wqk[(m0 + ty*2 + i)*256 + n0 + tx*4] =
                make_float4(p0.x, p0.y, p1.x, p1.y);
        }
    } else if (bid < 288) {
        int lane = t & 31, slice = t >> 5;
        int c = (bid - 256) * 32 + lane;
        float acc = 0.f;
        int kbase = slice * 128;
        #pragma unroll 8
        for (int i = 0; i < 128; i++)
            acc += Wq[(kbase + i)*1024 + c] * bk[kbase + i];
        sm[t] = acc; __syncthreads();
        if (t < 32)
            g_dots[(bid - 256)*32 + t] = sm[t] + sm[t+32] + sm[t+64] + sm[t+96];
    } else if (bid < 296) {
        int lane = t & 31, slice = t >> 5;
        int c = (bid - 288) * 32 + lane;
        float acc = 0.f;
        int kbase = slice * 128;
        #pragma unroll 8
        for (int i = 0; i < 128; i++)
            acc += Wk[(kbase + i)*256 + c] * bq[kbase + i];
        sm[t] = acc; __syncthreads();
        if (t < 32)
            g_dots[1024 + (bid - 288)*32 + t] = sm[t] + sm[t+32] + sm[t+64] + sm[t+96];
    } else if (bid == 296) {
        float acc = 0.f;
        for (int i = t; i < 512; i += 128) acc += bq[i] * bk[i];
        sm[t] = acc; __syncthreads();
        for (int st = 64; st > 0; st >>= 1) {
            if (t < st) sm[t] += sm[t + st];
            __syncthreads();
        }
        if (t == 0) g_dots[1280] = sm[0];
    } else {
        int r0 = (bid - 297) * 64;
        const float* src = xs_in + (size_t)r0 * 25;
        for (int i = t; i < 1600; i += 128) sm[i] = src[i];
        __syncthreads();
        if (t < 64) {
            float s = 0.f;
            #pragma unroll
            for (int w = 0; w < 25; w++) s += sm[t*25 + w];
            int o = r0 + t;
            int bc = o / 25, s_idx = o - bc * 25;
            g_pooledp[bc*32 + s_idx] = s * (1.0f / 25.0f);
        }
    }
}

// ---------------------------------------------------------------------------
// k_gemm1: [kq; v; bqk](b) = [Wqk; Wv; wkbq] @ pooledp_b + bias
// grid(17, 16), 256 thr (8 warps). BM=128, S=32, BK=32. thread 4m x 4s.
// ---------------------------------------------------------------------------
__global__ __launch_bounds__(256) void k_gemm1(const float* __restrict__ Wv,
                                               const float* __restrict__ bv) {
    __shared__ float As[32*132];
    __shared__ float Bs[32*32];
    int bx = blockIdx.x;
    int b  = blockIdx.y;
    int m0 = bx * 128;
    int t = threadIdx.x;
    int row = t >> 1, half = t & 1;
    int tx = t & 7, ty = t >> 3;
    unsigned long long acc2[4][2] = {};

    const float* arow;
    bool arow_valid;
    if (bx < 8)       { arow = g_wqk + (size_t)(m0 + row) * 256; arow_valid = true; }
    else if (bx < 16) { arow = Wv + (size_t)(m0 - 1024 + row) * 256; arow_valid = true; }
    else              { arow = g_dots + 1024; arow_valid = (row == 0); }

    for (int k0 = 0; k0 < 256; k0 += 32) {
        if (arow_valid) {
            #pragma unroll
            for (int u = 0; u < 4; u++) {
                int koff = half*16 + u*4;
                float4 a4 = *(const float4*)&arow[k0 + koff];
                As[(koff+0)*132 + row] = a4.x;
                As[(koff+1)*132 + row] = a4.y;
                As[(koff+2)*132 + row] = a4.z;
                As[(koff+3)*132 + row] = a4.w;
            }
        } else {
            #pragma unroll
            for (int u = 0; u < 4; u++) {
                int koff = half*16 + u*4;
                As[(koff+0)*132 + row] = 0.f;
                As[(koff+1)*132 + row] = 0.f;
                As[(koff+2)*132 + row] = 0.f;
                As[(koff+3)*132 + row] = 0.f;
            }
        }
        const float4* bsrc = (const float4*)(g_pooledp + ((b << 8) + k0) * 32);
        ((float4*)Bs)[t] = bsrc[t];
        __syncthreads();
        #pragma unroll 8
        for (int kk = 0; kk < 32; kk++) {
            float4 a4 = *(const float4*)&As[kk*132 + ty*4];
            ulonglong2 b2 = *(const ulonglong2*)&Bs[kk*32 + tx*4];
            unsigned long long pa[4] = {pack2(a4.x,a4.x), pack2(a4.y,a4.y),
                                        pack2(a4.z,a4.z), pack2(a4.w,a4.w)};
            #pragma unroll
            for (int i = 0; i < 4; i++) {
                fma2(acc2[i][0], pa[i], b2.x);
                fma2(acc2[i][1], pa[i], b2.y);
            }
        }
        __syncthreads();
    }
    int s0 = tx * 4;
    #pragma unroll
    for (int i = 0; i < 4; i++) {
        int m = m0 + ty*4 + i;
        float2 p0 = unpack2(acc2[i][0]), p1 = unpack2(acc2[i][1]);
        if (bx < 8) {
            float d = g_dots[m];
            *(float4*)&g_kq[((b << 10) + m)*32 + s0] =
                make_float4(p0.x+d, p0.y+d, p1.x+d, p1.y+d);
        } else if (bx < 16) {
            float d = bv[m - 1024];
            *(float4*)&g_v[((b << 10) + (m - 1024))*32 + s0] =
                make_float4(p0.x+d, p0.y+d, p1.x+d, p1.y+d);
        } else if (m == 2048) {
            float d = g_dots[1280];
            *(float4*)&g_bqk[b*32 + s0] =
                make_float4(p0.x+d, p0.y+d, p1.x+d, p1.y+d);
        }
    }
}

// ---------------------------------------------------------------------------
// k_energy: epart[z,b,n,s] = sum_{c in z-chunk} x[c,n]*kq[c,s], then the
// LAST z-block for each (n-tile,b) sums partials, softmaxes, writes attn_t.
// grid(7, 16, 4), 224 thr. thread 4n x 4s.
// ---------------------------------------------------------------------------
__global__ __launch_bounds__(224) void k_energy(const float* __restrict__ x) {
    __shared__ float xs[64*112];
    __shared__ float kqs[64*32];
    __shared__ int s_last;
    int n0 = blockIdx.x * 112;
    int b  = blockIdx.y;
    int z  = blockIdx.z;
    int t = threadIdx.x;
    int nq = t % 28, sg = t / 28;
    unsigned long long acc2[4][2] = {};

    for (int cz = 0; cz < 4; cz++) {
        int cbase = z * 256 + cz * 64;
        const float4* xsrc = (const float4*)x
            + (size_t)((b << 10) + cbase) * 196 + (n0 >> 2);
        #pragma unroll
        for (int u = 0; u < 8; u++) {
            int cc = sg + u * 8;
            *(float4*)&xs[cc*112 + nq*4] = xsrc[(size_t)cc*196 + nq];
        }
        const float4* kq4 = (const float4*)(g_kq + (size_t)((b << 10) + cbase)*32);
        float4* kqs4 = (float4*)kqs;
        kqs4[t] = kq4[t];
        if (t + 224 < 512) kqs4[t + 224] = kq4[t + 224];
        if (t < 512 - 448) kqs4[t + 448] = kq4[t + 448];
        __syncthreads();
        #pragma unroll 8
        for (int cc = 0; cc < 64; cc++) {
            float4 x4 = *(const float4*)&xs[cc*112 + nq*4];
            ulonglong2 k2 = *(const ulonglong2*)&kqs[cc*32 + sg*4];
            unsigned long long px[4] = {pack2(x4.x,x4.x), pack2(x4.y,x4.y),
                                        pack2(x4.z,x4.z), pack2(x4.w,x4.w)};
            #pragma unroll
            for (int i = 0; i < 4; i++) {
                fma2(acc2[i][0], px[i], k2.x);
                fma2(acc2[i][1], px[i], k2.y);
            }
        }
        __syncthreads();
    }
    float* ep = g_epart + (size_t)(z*16 + b)*784*32;
    #pragma unroll
    for (int i = 0; i < 4; i++) {
        int n = n0 + nq*4 + i;
        float2 p0 = unpack2(acc2[i][0]), p1 = unpack2(acc2[i][1]);
        *(float4*)&ep[(size_t)n*32 + sg*4] = make_float4(p0.x, p0.y, p1.x, p1.y);
    }

    // ---- last-block-arrives softmax ----
    __threadfence();
    __syncthreads();
    if (t == 0)
        s_last = (atomicAdd(&g_cnt[b*7 + blockIdx.x], 1) == 3) ? 1 : 0;
    __syncthreads();
    if (s_last == 0) return;

    if (t < 112) {
        int n = n0 + t;
        const size_t part = (size_t)16*784*32;
        const float* base = g_epart + ((size_t)b*784 + n)*32;
        float4 v0 = *(const float4*)base;
        float4 v1 = *(const float4*)(base + 4);
        float4 v2 = *(const float4*)(base + 8);
        float4 v3 = *(const float4*)(base + 12);
        float4 v4 = *(const float4*)(base + 16);
        float4 v5 = *(const float4*)(base + 20);
        float4 v6 = *(const float4*)(base + 24);
        #pragma unroll
        for (int zz = 1; zz < 4; zz++) {
            const float* bz = base + zz*part;
            float4 u0 = *(const float4*)bz;
            float4 u1 = *(const float4*)(bz + 4);
            float4 u2 = *(const float4*)(bz + 8);
            float4 u3 = *(const float4*)(bz + 12);
            float4 u4 = *(const float4*)(bz + 16);
            float4 u5 = *(const float4*)(bz + 20);
            float4 u6 = *(const float4*)(bz + 24);
            v0.x+=u0.x; v0.y+=u0.y; v0.z+=u0.z; v0.w+=u0.w;
            v1.x+=u1.x; v1.y+=u1.y; v1.z+=u1.z; v1.w+=u1.w;
            v2.x+=u2.x; v2.y+=u2.y; v2.z+=u2.z; v2.w+=u2.w;
            v3.x+=u3.x; v3.y+=u3.y; v3.z+=u3.z; v3.w+=u3.w;
            v4.x+=u4.x; v4.y+=u4.y; v4.z+=u4.z; v4.w+=u4.w;
            v5.x+=u5.x; v5.y+=u5.y; v5.z+=u5.z; v5.w+=u5.w;
            v6.x+=u6.x; v6.y+=u6.y; v6.z+=u6.z; v6.w+=u6.w;
        }
        float e[25] = {v0.x,v0.y,v0.z,v0.w, v1.x,v1.y,v1.z,v1.w,
                       v2.x,v2.y,v2.z,v2.w, v3.x,v3.y,v3.z,v3.w,
                       v4.x,v4.y,v4.z,v4.w, v5.x,v5.y,v5.z,v5.w, v6.x};
        float mx = -1e30f;
        #pragma unroll
        for (int s = 0; s < 25; s++) {
            e[s] += g_bqk[b*32 + s];
            mx = fmaxf(mx, e[s]);
        }
        float sum = 0.f;
        #pragma unroll
        for (int s = 0; s < 25; s++) { e[s] = __expf(e[s] - mx); sum += e[s]; }
        float inv = 1.f / sum;
        float* at = g_attn_t + (size_t)b*25*784 + n;
        #pragma unroll
        for (int s = 0; s < 25; s++) at[(size_t)s*784] = e[s] * inv;
    }
    if (t == 0) g_cnt[b*7 + blockIdx.x] = 0;
}

// ---------------------------------------------------------------------------
// k_out: out[c,n] = x[c,n] + gamma * sum_s v[c,s]*attn_t[s,n]
// grid(7 n-tiles of 112, 8 c-tiles of 128, 16 b), 224 thr. thread 8c x 8n.
// (R5-measured design: 32.4us, L1 64.7%)
// ---------------------------------------------------------------------------
__global__ __launch_bounds__(224, 2) void k_out(const float* __restrict__ x,
                                                const float* __restrict__ gamma_p,
                                                float* __restrict__ out) {
    __shared__ float attn_ts[25*112];   // [s][n] straight coalesced copy
    __shared__ float v_ts[25*132];      // [s][c] transpose load
    int n0 = blockIdx.x * 112;
    int c0 = blockIdx.y * 128;
    int b  = blockIdx.z;
    int t = threadIdx.x;

    // attn: 25 rows x 28 float4, straight copy
    const float4* at4 = (const float4*)(g_attn_t + (size_t)b*25*784) + (n0 >> 2);
    #pragma unroll
    for (int u = 0; u < 4; u++) {
        int i = t + u*224;
        if (i < 700) {
            int s = i / 28, q = i - s*28;
            ((float4*)attn_ts)[s*28 + q] = at4[(size_t)s*196 + q];
        }
    }
    // v: 128 rows x 8 quads, transposed into [s][c]
    const float4* v4p = (const float4*)(g_v + (size_t)((b << 10) + c0)*32);
    #pragma unroll
    for (int u = 0; u < 5; u++) {
        int i = t + u*224;
        if (i < 1024) {
            int row = i >> 3, q = i & 7;
            float4 a4 = v4p[row*8 + q];
            int s = q*4;
            if (s   < 25) v_ts[(s  )*132 + row] = a4.x;
            if (s+1 < 25) v_ts[(s+1)*132 + row] = a4.y;
            if (s+2 < 25) v_ts[(s+2)*132 + row] = a4.z;
            if (s+3 < 25) v_ts[(s+3)*132 + row] = a4.w;
        }
    }
    __syncthreads();

    int ng = t % 14, cq = t / 14;       // 14 n-octets x 16 c-octets
    unsigned long long acc2[8][4] = {};
    #pragma unroll
    for (int s = 0; s < 25; s++) {
        float4 vlo = *(const float4*)&v_ts[s*132 + cq*8];
        float4 vhi = *(const float4*)&v_ts[s*132 + cq*8 + 4];
        const ulonglong2* ap = (const ulonglong2*)&attn_ts[s*112 + ng*8];
        ulonglong2 A0 = ap[0], A1 = ap[1];
        unsigned long long pv[8] = {
            pack2(vlo.x,vlo.x), pack2(vlo.y,vlo.y),
            pack2(vlo.z,vlo.z), pack2(vlo.w,vlo.w),
            pack2(vhi.x,vhi.x), pack2(vhi.y,vhi.y),
            pack2(vhi.z,vhi.z), pack2(vhi.w,vhi.w)};
        #pragma unroll
        for (int i = 0; i < 8; i++) {
            fma2(acc2[i][0], pv[i], A0.x);
            fma2(acc2[i][1], pv[i], A0.y);
            fma2(acc2[i][2], pv[i], A1.x);
            fma2(acc2[i][3], pv[i], A1.y);
        }
    }
    float gamma = gamma_p[0];
    #pragma unroll
    for (int i = 0; i < 8; i++) {
        int c = c0 + cq*8 + i;
        size_t off = (size_t)((b << 10) + c)*784 + n0 + ng*8;
        const float* xr = x + off;
        float* orow = out + off;
        float2 q0 = unpack2(acc2[i][0]), q1 = unpack2(acc2[i][1]);
        float2 q2 = unpack2(acc2[i][2]), q3 = unpack2(acc2[i][3]);
        float4 xa = *(const float4*)xr;
        float4 xc = *(const float4*)(xr + 4);
        *(float4*)orow = make_float4(fmaf(gamma,q0.x,xa.x), fmaf(gamma,q0.y,xa.y),
                                     fmaf(gamma,q1.x,xa.z), fmaf(gamma,q1.y,xa.w));
        *(float4*)(orow+4) = make_float4(fmaf(gamma,q2.x,xc.x), fmaf(gamma,q2.y,xc.y),
                                         fmaf(gamma,q3.x,xc.z), fmaf(gamma,q3.y,xc.w));
    }
}

// ---------------------------------------------------------------------------
extern "C" void kernel_launch(void* const* d_in, const int* in_sizes, int n_in,
                              void* d_out, int out_size) {
    const float* x_rgb  = (const float*)d_in[0];
    const float* x_skel = (const float*)d_in[1];
    const float* Wq     = (const float*)d_in[2];
    const float* bq     = (const float*)d_in[3];
    const float* Wk     = (const float*)d_in[4];
    const float* bk     = (const float*)d_in[5];
    const float* Wv     = (const float*)d_in[6];
    const float* bv     = (const float*)d_in[7];
    const float* gamma  = (const float*)d_in[8];
    float* out = (float*)d_out;

    k_prep  <<<1897, 128>>>(Wq, bq, Wk, bk, x_skel);
    k_gemm1 <<<dim3(17, 16), 256>>>(Wv, bv);
    k_energy<<<dim3(7, 16, 4), 224>>>(x_rgb);
    k_out   <<<dim3(7, 8, 16), 224>>>(x_rgb, gamma, out);
}